// round 16
// baseline (speedup 1.0000x reference)
#include <cuda_runtime.h>
#include <cuda_fp16.h>
#include <math.h>
#include <stdint.h>

#define N_TOK 384
#define TDIM 768
#define VDIM 768
#define CDIM 1536
#define FF_DIM 2048
#define NH 4
#define NLAYERS 2
#define NCTA 148

// ---------------- fp32 scratch ----------------
#define OFF_X   0LL
#define OFF_X2  589824LL
#define OFF_SC  2949120LL
#define OFF_Y   4128768LL
#define OFF_A   5505024LL
#define OFF_C   5505792LL
#define OFF_RC  5506560LL
#define OFF_RL  5506944LL
#define OFF_CL  5507328LL
#define BUF_TOTAL 5507712LL
__device__ float g_buf[BUF_TOTAL];

// ---------------- fp16 scratch ----------------
#define HW_TQKV 0LL
#define HW_TOUT 3538944LL
#define HW_TFF1 4718592LL
#define HW_TFF2 7864320LL
#define HW_CQKV 11010048LL
#define HW_COUT 25165824LL
#define HW_CFF1 29884416LL
#define HW_CFF2 36175872LL
#define HA_QKV  42467328LL
#define HA_X    44236800LL
#define HA_O    44826624LL
#define HA_H    45416448LL
#define HBUF_TOTAL 46202880LL
__device__ __half g_hbuf[HBUF_TOTAL];

// ---------------- global barrier state ----------------
__device__ unsigned g_cnt = 0;
__device__ unsigned g_gen = 0;

__device__ __forceinline__ void gbar() {
    __syncthreads();
    __threadfence();
    if (threadIdx.x == 0) {
        unsigned gen = *(volatile unsigned*)&g_gen;
        unsigned arrived = atomicAdd(&g_cnt, 1) + 1;
        if (arrived == NCTA) {
            *(volatile unsigned*)&g_cnt = 0;
            __threadfence();
            atomicAdd(&g_gen, 1);
        } else {
            while (*(volatile unsigned*)&g_gen == gen) {}
            __threadfence();
        }
    }
    __syncthreads();
}

// ---------------- PDL ----------------
__device__ __forceinline__ void pdl_wait() {
    asm volatile("griddepcontrol.wait;" ::: "memory");
}
__device__ __forceinline__ void pdl_go() {
    asm volatile("griddepcontrol.launch_dependents;" ::: "memory");
}

// ---------------- helpers ----------------
__device__ __forceinline__ void mma16h(float* c, const unsigned* a, const unsigned* b) {
    asm volatile(
        "mma.sync.aligned.m16n8k16.row.col.f32.f16.f16.f32 "
        "{%0,%1,%2,%3},{%4,%5,%6,%7},{%8,%9},{%0,%1,%2,%3};"
        : "+f"(c[0]), "+f"(c[1]), "+f"(c[2]), "+f"(c[3])
        : "r"(a[0]), "r"(a[1]), "r"(a[2]), "r"(a[3]), "r"(b[0]), "r"(b[1]));
}
__device__ __forceinline__ void ldsm_x4(unsigned* r, uint32_t addr) {
    asm volatile("ldmatrix.sync.aligned.m8n8.x4.shared.b16 {%0,%1,%2,%3}, [%4];"
        : "=r"(r[0]), "=r"(r[1]), "=r"(r[2]), "=r"(r[3]) : "r"(addr));
}
__device__ __forceinline__ void ldsm_x4_t(unsigned* r, uint32_t addr) {
    asm volatile("ldmatrix.sync.aligned.m8n8.x4.trans.shared.b16 {%0,%1,%2,%3}, [%4];"
        : "=r"(r[0]), "=r"(r[1]), "=r"(r[2]), "=r"(r[3]) : "r"(addr));
}
__device__ __forceinline__ void cpa16(unsigned dst, const void* src) {
    asm volatile("cp.async.cg.shared.global [%0], [%1], 16;" :: "r"(dst), "l"(src));
}
__device__ __forceinline__ void cpa_commit() { asm volatile("cp.async.commit_group;"); }
template <int N>
__device__ __forceinline__ void cpa_wait() {
    asm volatile("cp.async.wait_group %0;" :: "n"(N));
}

// ---------------- merged weight conversion ----------------
struct ConvArgs {
    const float* src[8];
    long long dstOff[8];
    int cum[9];
};
__global__ void conv_all(ConvArgs a, __half* __restrict__ hbase) {
    int i = blockIdx.x * blockDim.x + threadIdx.x;
    if (i < a.cum[8]) {
#pragma unroll
        for (int k = 0; k < 8; k++) {
            if (i < a.cum[k + 1]) {
                int local = i - a.cum[k];
                float4 v = ((const float4*)a.src[k])[local];
                __half2* d = (__half2*)(hbase + a.dstOff[k]) + local * 2;
                d[0] = __floats2half2_rn(v.x, v.y);
                d[1] = __floats2half2_rn(v.z, v.w);
                break;
            }
        }
    }
    pdl_go();
}

// ============ GEMM tile (64x64, 128 thr): R13 winner as device fn ==========
#define HPAD 72
#define T16_BYTES (64 * HPAD * 2)
#define STG16 (2 * T16_BYTES)
#define GEMM_SMEM (3 * STG16)     // 55296

__device__ __forceinline__ void gemm_tile(
    const __half* __restrict__ A, int lda,
    const __half* __restrict__ W, int ldw,
    const float* __restrict__ Bias,
    float* __restrict__ C32, __half* __restrict__ C16, int ldc,
    int K, float alpha, int relu, int m0, int n0, char* smc)
{
    __half* hsm = (__half*)smc;
    uint32_t base = (uint32_t)__cvta_generic_to_shared(hsm);
    int tid = threadIdx.x;
    int warp = tid >> 5, lane = tid & 31;
    int g = lane >> 2, tg = lane & 3;
    int wm = (warp >> 1) * 32, wn = (warp & 1) * 32;

    int S = K / 64;
    float acc[2][4][4] = {};

    int aRow = (lane & 7) + ((lane >> 3) & 1) * 8;
    int aK   = ((lane >> 4) & 1) * 8;
    int bRow = ((lane >> 4) & 1) * 8 + (lane & 7);
    int bK   = ((lane >> 3) & 1) * 8;

    auto loadStage = [&](int s) {
        uint32_t st = base + (uint32_t)(s % 3) * STG16;
        const __half* Ak = A + (long long)s * 64;
        const __half* Wk = W + (long long)s * 64;
#pragma unroll
        for (int j = 0; j < 4; j++) {
            int c = tid + j * 128;
            int r = c >> 3, kq = (c & 7) * 8;
            cpa16(st + (uint32_t)r * 144u + (uint32_t)kq * 2u,
                  Ak + (long long)(m0 + r) * lda + kq);
        }
        uint32_t bs = st + T16_BYTES;
#pragma unroll
        for (int j = 0; j < 4; j++) {
            int c = tid + j * 128;
            int r = c >> 3, kq = (c & 7) * 8;
            cpa16(bs + (uint32_t)r * 144u + (uint32_t)kq * 2u,
                  Wk + (long long)(n0 + r) * ldw + kq);
        }
        cpa_commit();
    };

    loadStage(0);
    loadStage(1);

    for (int s = 0; s < S; s++) {
        if (s == S - 1) cpa_wait<0>(); else cpa_wait<1>();
        __syncthreads();
        if (s + 2 < S) loadStage(s + 2);
        else cpa_commit();

        uint32_t aB = base + (uint32_t)(s % 3) * STG16;
        uint32_t bB = aB + T16_BYTES;

        unsigned afr[2][2][4], bfr[2][2][4];
        auto loadFrag = [&](int ks, int buf) {
            int kb = ks * 16;
#pragma unroll
            for (int mt = 0; mt < 2; mt++)
                ldsm_x4(afr[buf][mt],
                        aB + (uint32_t)(wm + mt * 16 + aRow) * 144u
                           + (uint32_t)(kb + aK) * 2u);
#pragma unroll
            for (int p = 0; p < 2; p++)
                ldsm_x4(bfr[buf][p],
                        bB + (uint32_t)(wn + p * 16 + bRow) * 144u
                           + (uint32_t)(kb + bK) * 2u);
        };

        loadFrag(0, 0);
#pragma unroll
        for (int ks = 0; ks < 4; ks++) {
            int buf = ks & 1;
            if (ks < 3) loadFrag(ks + 1, buf ^ 1);
#pragma unroll
            for (int mt = 0; mt < 2; mt++)
#pragma unroll
                for (int nt = 0; nt < 4; nt++)
                    mma16h(acc[mt][nt], afr[buf][mt], &bfr[buf][nt >> 1][(nt & 1) * 2]);
        }
        __syncthreads();
    }

#pragma unroll
    for (int mt = 0; mt < 2; mt++) {
#pragma unroll
        for (int nt = 0; nt < 4; nt++) {
            int col = n0 + wn + nt * 8 + 2 * tg;
            float b0 = 0.f, b1 = 0.f;
            if (Bias) { b0 = Bias[col]; b1 = Bias[col + 1]; }
            int row = m0 + wm + mt * 16 + g;
            float v00 = acc[mt][nt][0] * alpha + b0;
            float v01 = acc[mt][nt][1] * alpha + b1;
            float v10 = acc[mt][nt][2] * alpha + b0;
            float v11 = acc[mt][nt][3] * alpha + b1;
            if (relu) {
                v00 = fmaxf(v00, 0.f); v01 = fmaxf(v01, 0.f);
                v10 = fmaxf(v10, 0.f); v11 = fmaxf(v11, 0.f);
            }
            if (C32) {
                *(float2*)&C32[(long long)row * ldc + col] = make_float2(v00, v01);
                *(float2*)&C32[(long long)(row + 8) * ldc + col] = make_float2(v10, v11);
            }
            if (C16) {
                *(__half2*)&C16[(long long)row * ldc + col] = __floats2half2_rn(v00, v01);
                *(__half2*)&C16[(long long)(row + 8) * ldc + col] = __floats2half2_rn(v10, v11);
            }
        }
    }
}

// ============ fused softmax + attn@V tile (R12 winner as device fn) ========
#define PPITCH 392
#define P_BYTES (64 * PPITCH * 2)
#define BV_BYTES (384 * 72 * 2)
#define ATT_SMEM (P_BYTES + BV_BYTES)   // 105472

__device__ __forceinline__ void attn_tile(
    const float* __restrict__ sc,    // head-offset scores [N][N]
    const __half* __restrict__ Vb,   // V panel base (head+col offset), ld = 3*d
    __half* __restrict__ O, int d,
    int m0, int col0, char* smc)
{
    __half* P = (__half*)smc;
    uint32_t Pb = (uint32_t)__cvta_generic_to_shared(P);
    uint32_t Bb = Pb + P_BYTES;

    int tid = threadIdx.x;
    int warp = tid >> 5, lane = tid & 31;
    int g = lane >> 2, tg = lane & 3;
    int wm = (warp >> 1) * 32, wn = (warp & 1) * 32;

#pragma unroll
    for (int j = 0; j < 24; j++) {
        int c = tid + j * 128;
        int k = c >> 3, q = (c & 7) * 8;
        cpa16(Bb + (uint32_t)k * 144u + (uint32_t)q * 2u,
              Vb + (long long)k * (3 * d) + q);
    }
    cpa_commit();

    {
        int r = tid >> 1, h = tid & 1;
        const float* row = sc + (long long)(m0 + r) * N_TOK + h * 192;
        float mx = -1e30f;
        for (int c = 0; c < 192; c += 4) {
            float4 v = __ldcg((const float4*)(row + c));
            mx = fmaxf(mx, fmaxf(fmaxf(v.x, v.y), fmaxf(v.z, v.w)));
        }
        mx = fmaxf(mx, __shfl_xor_sync(0xffffffffu, mx, 1));
        __half* pr = P + r * PPITCH + h * 192;
        float sm = 0.f;
        for (int c = 0; c < 192; c += 4) {
            float4 v = __ldcg((const float4*)(row + c));
            float e0 = expf(v.x - mx), e1 = expf(v.y - mx);
            float e2 = expf(v.z - mx), e3 = expf(v.w - mx);
            sm += (e0 + e1) + (e2 + e3);
            *(__half2*)(pr + c)     = __floats2half2_rn(e0, e1);
            *(__half2*)(pr + c + 2) = __floats2half2_rn(e2, e3);
        }
        sm += __shfl_xor_sync(0xffffffffu, sm, 1);
        float inv = 1.0f / sm;
        __half2 hinv = __floats2half2_rn(inv, inv);
        for (int c = 0; c < 192; c += 2) {
            __half2* p2 = (__half2*)(pr + c);
            *p2 = __hmul2(*p2, hinv);
        }
    }
    cpa_wait<0>();
    __syncthreads();

    int aRow = (lane & 7) + ((lane >> 3) & 1) * 8;
    int aK   = ((lane >> 4) & 1) * 8;
    int tKr  = ((lane >> 3) & 1) * 8 + (lane & 7);
    int tNc  = ((lane >> 4) & 1) * 8;

    float acc[2][4][4] = {};
    unsigned afr[2][2][4], bfr[2][2][4];

    auto loadFrag = [&](int ks, int buf) {
        int kb = ks * 16;
#pragma unroll
        for (int mt = 0; mt < 2; mt++)
            ldsm_x4(afr[buf][mt],
                    Pb + (uint32_t)(wm + mt * 16 + aRow) * 784u
                       + (uint32_t)(kb + aK) * 2u);
#pragma unroll
        for (int p = 0; p < 2; p++)
            ldsm_x4_t(bfr[buf][p],
                      Bb + (uint32_t)(kb + tKr) * 144u
                         + (uint32_t)(wn + p * 16 + tNc) * 2u);
    };

    loadFrag(0, 0);
#pragma unroll
    for (int ks = 0; ks < 24; ks++) {
        int buf = ks & 1;
        if (ks < 23) loadFrag(ks + 1, buf ^ 1);
#pragma unroll
        for (int mt = 0; mt < 2; mt++)
#pragma unroll
            for (int nt = 0; nt < 4; nt++)
                mma16h(acc[mt][nt], afr[buf][mt], &bfr[buf][nt >> 1][(nt & 1) * 2]);
    }
    __syncthreads();

#pragma unroll
    for (int mt = 0; mt < 2; mt++) {
#pragma unroll
        for (int nt = 0; nt < 4; nt++) {
            int row = m0 + wm + mt * 16 + g;
            int col = col0 + wn + nt * 8 + 2 * tg;
            *(__half2*)&O[(long long)row * d + col] =
                __floats2half2_rn(acc[mt][nt][0], acc[mt][nt][1]);
            *(__half2*)&O[(long long)(row + 8) * d + col] =
                __floats2half2_rn(acc[mt][nt][2], acc[mt][nt][3]);
        }
    }
}

// ============ LN row (128 threads) ============
__device__ __forceinline__ void ln_row(
    float* __restrict__ x, __half* __restrict__ xh,
    const float* __restrict__ delta,
    const float* __restrict__ s, const float* __restrict__ b,
    int d, float* red)
{
    int tid = threadIdx.x;
    float sum = 0.f;
    for (int j = tid; j < d; j += 128) {
        float v = __ldcg(x + j) + __ldcg(delta + j);
        x[j] = v; sum += v;
    }
    red[tid] = sum; __syncthreads();
    for (int off = 64; off; off >>= 1) {
        if (tid < off) red[tid] += red[tid + off];
        __syncthreads();
    }
    float mean = red[0] / d; __syncthreads();
    float s2 = 0.f;
    for (int j = tid; j < d; j += 128) {
        float v = __ldcg(x + j) - mean; s2 += v * v;
    }
    red[tid] = s2; __syncthreads();
    for (int off = 64; off; off >>= 1) {
        if (tid < off) red[tid] += red[tid + off];
        __syncthreads();
    }
    float inv = rsqrtf(red[0] / d + 1e-5f);
    __syncthreads();
    for (int j = tid; j < d; j += 128) {
        float v = (__ldcg(x + j) - mean) * inv * s[j] + b[j];
        x[j] = v;
        xh[j] = __float2half(v);
    }
    __syncthreads();
}

// ============ GEMM phase (tile loop) ============
__device__ void gemm_phase(
    const __half* A, int lda, long long aZ,
    const __half* W, int ldw, long long wZ,
    const float* Bias, float* C32, __half* C16, int ldc, long long cZ,
    int K, float alpha, int relu, int nX, int nZ, char* sm)
{
    int ntiles = nX * 6 * nZ;
    for (int t = blockIdx.x; t < ntiles; t += NCTA) {
        int z = t / (nX * 6);
        int rr = t % (nX * 6);
        int n0 = (rr % nX) * 64;
        int m0 = (rr / nX) * 64;
        gemm_tile(A + z * aZ, lda, W + z * wZ, ldw, Bias,
                  C32 ? C32 + z * cZ : (float*)0,
                  C16 ? C16 + z * cZ : (__half*)0,
                  ldc, K, alpha, relu, m0, n0, sm);
        __syncthreads();
    }
}

// ============ megakernel args ============
struct EncP {
    const __half *qkv_h, *out_h, *ff1_h, *ff2_h;
    const float *qkv_b, *out_b, *ln1_s, *ln1_b, *ff1_b, *ff2_b, *ln2_s, *ln2_b;
};
struct MegaArgs {
    const float *text, *vision;
    EncP tw, cw;
    float *x, *x2, *sc, *y;
    __half *qkvh, *xh, *oh, *hh;
};

__device__ void run_enc(const MegaArgs& A, const EncP& w, float* x, int d, char* sm) {
    float* red = (float*)sm;
    const int hd = d / NH;
    const float scale = rsqrtf((float)hd);
    for (int l = 0; l < NLAYERS; l++) {
        // qkv (fp16 out)
        gemm_phase(A.xh, d, 0, w.qkv_h + (long long)l * 3 * d * d, d, 0,
                   w.qkv_b + (long long)l * 3 * d, (float*)0, A.qkvh, 3 * d, 0,
                   d, 1.f, 0, 3 * d / 64, 1, sm);
        gbar();
        // scores (fp32, scaled)
        gemm_phase(A.qkvh, 3 * d, hd, A.qkvh + d, 3 * d, hd,
                   (const float*)0, A.sc, (__half*)0, N_TOK, (long long)N_TOK * N_TOK,
                   hd, scale, 0, 6, NH, sm);
        gbar();
        // fused softmax + attn@V
        {
            int nXa = hd / 64;
            int ntiles = nXa * 6 * NH;
            for (int t = blockIdx.x; t < ntiles; t += NCTA) {
                int z = t / (nXa * 6);
                int rr = t % (nXa * 6);
                int nc0 = (rr % nXa) * 64;
                int m0 = (rr / nXa) * 64;
                attn_tile(A.sc + (long long)z * N_TOK * N_TOK,
                          A.qkvh + 2 * d + (long long)z * hd + nc0,
                          A.oh, d, m0, z * hd + nc0, sm);
                __syncthreads();
            }
        }
        gbar();
        // out proj (fp32 out)
        gemm_phase(A.oh, d, 0, w.out_h + (long long)l * d * d, d, 0,
                   w.out_b + (long long)l * d, A.y, (__half*)0, d, 0,
                   d, 1.f, 0, d / 64, 1, sm);
        gbar();
        // LN1
        for (int r = blockIdx.x; r < N_TOK; r += NCTA)
            ln_row(x + (long long)r * d, A.xh + (long long)r * d,
                   A.y + (long long)r * d,
                   w.ln1_s + (long long)l * d, w.ln1_b + (long long)l * d, d, red);
        gbar();
        // ff1 (fp16 out, relu)
        gemm_phase(A.xh, d, 0, w.ff1_h + (long long)l * FF_DIM * d, d, 0,
                   w.ff1_b + (long long)l * FF_DIM, (float*)0, A.hh, FF_DIM, 0,
                   d, 1.f, 1, FF_DIM / 64, 1, sm);
        gbar();
        // ff2 (fp32 out)
        gemm_phase(A.hh, FF_DIM, 0, w.ff2_h + (long long)l * d * FF_DIM, FF_DIM, 0,
                   w.ff2_b + (long long)l * d, A.y, (__half*)0, d, 0,
                   FF_DIM, 1.f, 0, d / 64, 1, sm);
        gbar();
        // LN2
        for (int r = blockIdx.x; r < N_TOK; r += NCTA)
            ln_row(x + (long long)r * d, A.xh + (long long)r * d,
                   A.y + (long long)r * d,
                   w.ln2_s + (long long)l * d, w.ln2_b + (long long)l * d, d, red);
        gbar();
    }
}

__global__ void __launch_bounds__(128) mega(MegaArgs A) {
    extern __shared__ char sm[];
    pdl_wait();
    int tid = threadIdx.x;

    // copy phase: text -> x, xh
    for (int i = blockIdx.x * 128 + tid; i < N_TOK * TDIM; i += NCTA * 128) {
        float v = A.text[i];
        A.x[i] = v; A.xh[i] = __float2half(v);
    }
    gbar();

    run_enc(A, A.tw, A.x, TDIM, sm);

    // concat phase: [x | vision] -> x2, xh
    for (int i = blockIdx.x * 128 + tid; i < N_TOK * CDIM; i += NCTA * 128) {
        int r = i / CDIM, c = i % CDIM;
        float v = (c < TDIM) ? __ldcg(A.x + (long long)r * TDIM + c)
                             : A.vision[(long long)r * VDIM + (c - TDIM)];
        A.x2[i] = v; A.xh[i] = __float2half(v);
    }
    gbar();

    run_enc(A, A.cw, A.x2, CDIM, sm);
    pdl_go();
}

// ---------------- tail kernels (unchanged) ----------------
__global__ void lin_kernel(const float* __restrict__ x, const float* __restrict__ w,
                           const float* __restrict__ b, float* __restrict__ a,
                           float* __restrict__ c) {
    pdl_wait();
    int i = blockIdx.x;
    const float* xr = x + (long long)i * CDIM;
    __shared__ float red[4][256];
    int tid = threadIdx.x;
    float s0 = 0, s1 = 0, s2 = 0, s3 = 0;
    for (int k = tid; k < CDIM; k += 256) {
        float xv = xr[k];
        s0 += xv * w[k];
        s1 += xv * w[2 * CDIM + k];
        s2 += xv * w[CDIM + k];
        s3 += xv * w[2 * CDIM + CDIM + k];
    }
    red[0][tid] = s0; red[1][tid] = s1; red[2][tid] = s2; red[3][tid] = s3;
    __syncthreads();
    for (int off = 128; off; off >>= 1) {
        if (tid < off) {
            red[0][tid] += red[0][tid + off];
            red[1][tid] += red[1][tid + off];
            red[2][tid] += red[2][tid + off];
            red[3][tid] += red[3][tid + off];
        }
        __syncthreads();
    }
    if (tid == 0) {
        a[2 * i]     = red[0][0] + b[0];
        a[2 * i + 1] = red[1][0] + b[1];
        c[2 * i]     = red[2][0];
        c[2 * i + 1] = red[3][0];
    }
    pdl_go();
}

__global__ void pair_kernel(const float* __restrict__ a, const float* __restrict__ c,
                            const int* __restrict__ gt, float* __restrict__ probs,
                            float* __restrict__ rowcell, float* __restrict__ rowlink) {
    pdl_wait();
    int i = blockIdx.x, j = threadIdx.x;
    float l0 = a[2 * i] + c[2 * j];
    float l1 = a[2 * i + 1] + c[2 * j + 1];
    float m = fmaxf(l0, l1);
    float e0 = expf(l0 - m), e1 = expf(l1 - m);
    float inv = 1.0f / (e0 + e1);
    float p0 = e0 * inv, p1 = e1 * inv;
    long long idx = ((long long)i * N_TOK + j) * 2;
    probs[idx] = p0; probs[idx + 1] = p1;
    float mm = fmaxf(p0, p1);
    float lse = mm + logf(expf(p0 - mm) + expf(p1 - mm));
    float pg = gt[i * N_TOK + j] ? p1 : p0;
    float cell = lse - pg;

    __shared__ float red[512];
    red[j] = cell;
    if (j < 128) red[384 + j] = 0.f;
    __syncthreads();
    for (int off = 256; off; off >>= 1) {
        if (j < off) red[j] += red[j + off];
        __syncthreads();
    }
    if (j == 0) rowcell[i] = red[0];
    __syncthreads();
    red[j] = p1;
    if (j < 128) red[384 + j] = 0.f;
    __syncthreads();
    for (int off = 256; off; off >>= 1) {
        if (j < off) red[j] += red[j + off];
        __syncthreads();
    }
    if (j == 0) rowlink[i] = red[0];
    pdl_go();
}

__global__ void col_kernel(const float* __restrict__ probs, float* __restrict__ collink) {
    pdl_wait();
    int j = blockIdx.x; int tid = threadIdx.x;
    float s = 0.f;
    for (int i = tid; i < N_TOK; i += 128) s += probs[((long long)i * N_TOK + j) * 2 + 1];
    __shared__ float red[128];
    red[tid] = s; __syncthreads();
    for (int off = 64; off; off >>= 1) {
        if (tid < off) red[tid] += red[tid + off];
        __syncthreads();
    }
    if (tid == 0) collink[j] = red[0];
    pdl_go();
}

__global__ void final_kernel(const float* __restrict__ rowcell, const float* __restrict__ rowlink,
                             const float* __restrict__ collink, float* __restrict__ out,
                             int out_size) {
    pdl_wait();
    __shared__ float r1[512], r2[512];
    int tid = threadIdx.x;
    r1[tid] = (tid < N_TOK) ? rowcell[tid] : 0.f;
    r2[tid] = (tid < N_TOK - 1) ? fabsf(rowlink[tid] + collink[tid] - 1.0f) : 0.f;
    __syncthreads();
    for (int off = 256; off; off >>= 1) {
        if (tid < off) { r1[tid] += r1[tid + off]; r2[tid] += r2[tid + off]; }
        __syncthreads();
    }
    if (tid == 0 && out_size >= N_TOK * N_TOK * 2 + 2) {
        out[N_TOK * N_TOK * 2]     = r1[0] / (float)N_TOK;
        out[N_TOK * N_TOK * 2 + 1] = r2[0];
    }
}

// ---------------- host orchestration ----------------
static cudaLaunchAttribute g_attr[1];
template <typename F, typename... Args>
static inline void pl(F f, dim3 gr, dim3 bl, size_t sm, Args... args) {
    cudaLaunchConfig_t c = {};
    c.gridDim = gr; c.blockDim = bl; c.dynamicSmemBytes = sm; c.stream = 0;
    g_attr[0].id = cudaLaunchAttributeProgrammaticStreamSerialization;
    g_attr[0].val.programmaticStreamSerializationAllowed = 1;
    c.attrs = g_attr; c.numAttrs = 1;
    cudaLaunchKernelEx(&c, f, args...);
}

extern "C" void kernel_launch(void* const* d_in, const int* in_sizes, int n_in,
                              void* d_out, int out_size) {
    const float* text   = (const float*)d_in[0];
    const float* vision = (const float*)d_in[1];
    const int*   gt     = (const int*)d_in[2];
    const float* lin_w  = (const float*)d_in[27];
    const float* lin_b  = (const float*)d_in[28];

    static int inited = 0;
    if (!inited) {
        cudaFuncSetAttribute(mega, cudaFuncAttributeMaxDynamicSharedMemorySize, ATT_SMEM);
        inited = 1;
    }

    float* buf = nullptr;
    cudaGetSymbolAddress((void**)&buf, g_buf);
    __half* hb = nullptr;
    cudaGetSymbolAddress((void**)&hb, g_hbuf);

    float* x    = buf + OFF_X;
    float* x2   = buf + OFF_X2;
    float* sc   = buf + OFF_SC;
    float* y    = buf + OFF_Y;
    float* ga   = buf + OFF_A;
    float* gc   = buf + OFF_C;
    float* rcel = buf + OFF_RC;
    float* rlnk = buf + OFF_RL;
    float* clnk = buf + OFF_CL;

    ConvArgs ca;
    const long long offs[8] = {HW_TQKV, HW_TOUT, HW_TFF1, HW_TFF2,
                               HW_CQKV, HW_COUT, HW_CFF1, HW_CFF2};
    const int srcs[8] = {3, 5, 9, 11, 15, 17, 21, 23};
    const long long ns[8] = {3538944LL, 1179648LL, 3145728LL, 3145728LL,
                             14155776LL, 4718592LL, 6291456LL, 6291456LL};
    ca.cum[0] = 0;
    for (int i = 0; i < 8; i++) {
        ca.src[i] = (const float*)d_in[srcs[i]];
        ca.dstOff[i] = offs[i];
        ca.cum[i + 1] = ca.cum[i] + (int)(ns[i] / 4);
    }
    pl(conv_all, dim3((ca.cum[8] + 255) / 256), dim3(256), 0, ca, hb);

    MegaArgs ma;
    ma.text = text; ma.vision = vision;
    ma.tw = { hb + HW_TQKV, hb + HW_TOUT, hb + HW_TFF1, hb + HW_TFF2,
              (const float*)d_in[4], (const float*)d_in[6],
              (const float*)d_in[7], (const float*)d_in[8],
              (const float*)d_in[10], (const float*)d_in[12],
              (const float*)d_in[13], (const float*)d_in[14] };
    ma.cw = { hb + HW_CQKV, hb + HW_COUT, hb + HW_CFF1, hb + HW_CFF2,
              (const float*)d_in[16], (const float*)d_in[18],
              (const float*)d_in[19], (const float*)d_in[20],
              (const float*)d_in[22], (const float*)d_in[24],
              (const float*)d_in[25], (const float*)d_in[26] };
    ma.x = x; ma.x2 = x2; ma.sc = sc; ma.y = y;
    ma.qkvh = hb + HA_QKV; ma.xh = hb + HA_X; ma.oh = hb + HA_O; ma.hh = hb + HA_H;

    pl(mega, dim3(NCTA), dim3(128), (size_t)ATT_SMEM, ma);

    pl(lin_kernel, dim3(N_TOK), dim3(256), 0, (const float*)x2, lin_w, lin_b, ga, gc);

    float* out = (float*)d_out;
    pl(pair_kernel, dim3(N_TOK), dim3(N_TOK), 0,
       (const float*)ga, (const float*)gc, gt, out, rcel, rlnk);
    pl(col_kernel, dim3(N_TOK), dim3(128), 0, (const float*)out, clnk);
    pl(final_kernel, dim3(1), dim3(512), 0,
       (const float*)rcel, (const float*)rlnk, (const float*)clnk, out, out_size);
}

// round 17
// speedup vs baseline: 1.5409x; 1.5409x over previous
#include <cuda_runtime.h>
#include <cuda_fp16.h>
#include <math.h>
#include <stdint.h>

#define N_TOK 384
#define TDIM 768
#define VDIM 768
#define CDIM 1536
#define FF_DIM 2048
#define NH 4
#define NLAYERS 2

// ---------------- fp32 scratch ----------------
#define OFF_X   0LL
#define OFF_X2  589824LL
#define OFF_SC  2949120LL
#define OFF_Y   4128768LL
#define OFF_A   5505024LL
#define OFF_C   5505792LL
#define OFF_RC  5506560LL
#define OFF_RL  5506944LL
#define OFF_CL  5507328LL
#define BUF_TOTAL 5507712LL
__device__ float g_buf[BUF_TOTAL];

// ---------------- fp16 scratch (converted weights + activation shadows) ----
#define HW_TQKV 0LL
#define HW_TOUT 3538944LL
#define HW_TFF1 4718592LL
#define HW_TFF2 7864320LL
#define HW_CQKV 11010048LL
#define HW_COUT 25165824LL
#define HW_CFF1 29884416LL
#define HW_CFF2 36175872LL
#define HA_QKV  42467328LL
#define HA_X    44236800LL
#define HA_O    44826624LL
#define HA_H    45416448LL
#define HBUF_TOTAL 46202880LL
__device__ __half g_hbuf[HBUF_TOTAL];

// ---------------- PDL ----------------
__device__ __forceinline__ void pdl_wait() {
    asm volatile("griddepcontrol.wait;" ::: "memory");
}
__device__ __forceinline__ void pdl_go() {
    asm volatile("griddepcontrol.launch_dependents;" ::: "memory");
}

// ---------------- helpers ----------------
__device__ __forceinline__ void mma16h(float* c, const unsigned* a, const unsigned* b) {
    asm volatile(
        "mma.sync.aligned.m16n8k16.row.col.f32.f16.f16.f32 "
        "{%0,%1,%2,%3},{%4,%5,%6,%7},{%8,%9},{%0,%1,%2,%3};"
        : "+f"(c[0]), "+f"(c[1]), "+f"(c[2]), "+f"(c[3])
        : "r"(a[0]), "r"(a[1]), "r"(a[2]), "r"(a[3]), "r"(b[0]), "r"(b[1]));
}
__device__ __forceinline__ void ldsm_x4(unsigned* r, uint32_t addr) {
    asm volatile("ldmatrix.sync.aligned.m8n8.x4.shared.b16 {%0,%1,%2,%3}, [%4];"
        : "=r"(r[0]), "=r"(r[1]), "=r"(r[2]), "=r"(r[3]) : "r"(addr));
}
__device__ __forceinline__ void ldsm_x4_t(unsigned* r, uint32_t addr) {
    asm volatile("ldmatrix.sync.aligned.m8n8.x4.trans.shared.b16 {%0,%1,%2,%3}, [%4];"
        : "=r"(r[0]), "=r"(r[1]), "=r"(r[2]), "=r"(r[3]) : "r"(addr));
}
__device__ __forceinline__ void cpa16(unsigned dst, const void* src) {
    asm volatile("cp.async.cg.shared.global [%0], [%1], 16;" :: "r"(dst), "l"(src));
}
__device__ __forceinline__ void cpa_commit() { asm volatile("cp.async.commit_group;"); }
template <int N>
__device__ __forceinline__ void cpa_wait() {
    asm volatile("cp.async.wait_group %0;" :: "n"(N));
}

// ---------------- merged weight conversion + text copy (all pure inputs) ---
struct ConvArgs {
    const float* src[8];
    long long dstOff[8];
    int cum[9];
    const float* text;
    float* x;
    __half* xh;
    int textN4;   // N_TOK*TDIM/4
};
__global__ void conv_all(ConvArgs a, __half* __restrict__ hbase) {
    int i = blockIdx.x * blockDim.x + threadIdx.x;
    if (i < a.cum[8]) {
#pragma unroll
        for (int k = 0; k < 8; k++) {
            if (i < a.cum[k + 1]) {
                int local = i - a.cum[k];
                float4 v = ((const float4*)a.src[k])[local];
                __half2* d = (__half2*)(hbase + a.dstOff[k]) + local * 2;
                d[0] = __floats2half2_rn(v.x, v.y);
                d[1] = __floats2half2_rn(v.z, v.w);
                break;
            }
        }
    } else {
        int local = i - a.cum[8];
        if (local < a.textN4) {
            float4 v = ((const float4*)a.text)[local];
            ((float4*)a.x)[local] = v;
            __half2* d = (__half2*)a.xh + local * 2;
            d[0] = __floats2half2_rn(v.x, v.y);
            d[1] = __floats2half2_rn(v.z, v.w);
        }
    }
    pdl_go();
}

__global__ void concat_k(float* __restrict__ dst, __half* __restrict__ dsth,
                         const float* __restrict__ te, const float* __restrict__ vis) {
    pdl_wait();
    int i = blockIdx.x * blockDim.x + threadIdx.x;
    if (i < N_TOK * CDIM) {
        int r = i / CDIM, c = i % CDIM;
        float v = (c < TDIM) ? te[r * TDIM + c] : vis[r * VDIM + (c - TDIM)];
        dst[i] = v; dsth[i] = __float2half(v);
    }
    pdl_go();
}

// ============ fp16 NT GEMM: 64x64 tile, 128 threads (R13 champion) =========
#define HPAD 72
#define T16_BYTES (64 * HPAD * 2)
#define STG16 (2 * T16_BYTES)
#define H_SMEM (3 * STG16)

__global__ void __launch_bounds__(128) h16_nt(
    const __half* __restrict__ A, int lda, long long aZ,
    const __half* __restrict__ W, int ldw, long long wZ,
    const float* __restrict__ Bias,
    float* __restrict__ C32, __half* __restrict__ C16,
    int ldc, long long cZ,
    int K, float alpha, int relu)
{
    extern __shared__ __half hsm[];
    uint32_t base = (uint32_t)__cvta_generic_to_shared(hsm);

    pdl_wait();
    A += blockIdx.z * aZ; W += blockIdx.z * wZ;

    int tid = threadIdx.x;
    int warp = tid >> 5, lane = tid & 31;
    int g = lane >> 2, tg = lane & 3;
    int wm = (warp >> 1) * 32, wn = (warp & 1) * 32;
    int m0 = blockIdx.y * 64, n0 = blockIdx.x * 64;

    int S = K / 64;
    float acc[2][4][4] = {};

    int aRow = (lane & 7) + ((lane >> 3) & 1) * 8;
    int aK   = ((lane >> 4) & 1) * 8;
    int bRow = ((lane >> 4) & 1) * 8 + (lane & 7);
    int bK   = ((lane >> 3) & 1) * 8;

    auto loadStage = [&](int s) {
        uint32_t st = base + (uint32_t)(s % 3) * STG16;
        const __half* Ak = A + (long long)s * 64;
        const __half* Wk = W + (long long)s * 64;
#pragma unroll
        for (int j = 0; j < 4; j++) {
            int c = tid + j * 128;
            int r = c >> 3, kq = (c & 7) * 8;
            cpa16(st + (uint32_t)r * 144u + (uint32_t)kq * 2u,
                  Ak + (long long)(m0 + r) * lda + kq);
        }
        uint32_t bs = st + T16_BYTES;
#pragma unroll
        for (int j = 0; j < 4; j++) {
            int c = tid + j * 128;
            int r = c >> 3, kq = (c & 7) * 8;
            cpa16(bs + (uint32_t)r * 144u + (uint32_t)kq * 2u,
                  Wk + (long long)(n0 + r) * ldw + kq);
        }
        cpa_commit();
    };

    loadStage(0);
    loadStage(1);

    for (int s = 0; s < S; s++) {
        if (s == S - 1) cpa_wait<0>(); else cpa_wait<1>();
        __syncthreads();
        if (s + 2 < S) loadStage(s + 2);
        else cpa_commit();

        uint32_t aB = base + (uint32_t)(s % 3) * STG16;
        uint32_t bB = aB + T16_BYTES;

        unsigned afr[2][2][4], bfr[2][2][4];
        auto loadFrag = [&](int ks, int buf) {
            int kb = ks * 16;
#pragma unroll
            for (int mt = 0; mt < 2; mt++)
                ldsm_x4(afr[buf][mt],
                        aB + (uint32_t)(wm + mt * 16 + aRow) * 144u
                           + (uint32_t)(kb + aK) * 2u);
#pragma unroll
            for (int p = 0; p < 2; p++)
                ldsm_x4(bfr[buf][p],
                        bB + (uint32_t)(wn + p * 16 + bRow) * 144u
                           + (uint32_t)(kb + bK) * 2u);
        };

        loadFrag(0, 0);
#pragma unroll
        for (int ks = 0; ks < 4; ks++) {
            int buf = ks & 1;
            if (ks < 3) loadFrag(ks + 1, buf ^ 1);
#pragma unroll
            for (int mt = 0; mt < 2; mt++)
#pragma unroll
                for (int nt = 0; nt < 4; nt++)
                    mma16h(acc[mt][nt], afr[buf][mt], &bfr[buf][nt >> 1][(nt & 1) * 2]);
        }
        __syncthreads();
    }

    float* C32p = C32 ? C32 + blockIdx.z * cZ : (float*)0;
    __half* C16p = C16 ? C16 + blockIdx.z * cZ : (__half*)0;
#pragma unroll
    for (int mt = 0; mt < 2; mt++) {
#pragma unroll
        for (int nt = 0; nt < 4; nt++) {
            int col = n0 + wn + nt * 8 + 2 * tg;
            float b0 = 0.f, b1 = 0.f;
            if (Bias) { b0 = Bias[col]; b1 = Bias[col + 1]; }
            int row = m0 + wm + mt * 16 + g;
            float v00 = acc[mt][nt][0] * alpha + b0;
            float v01 = acc[mt][nt][1] * alpha + b1;
            float v10 = acc[mt][nt][2] * alpha + b0;
            float v11 = acc[mt][nt][3] * alpha + b1;
            if (relu) {
                v00 = fmaxf(v00, 0.f); v01 = fmaxf(v01, 0.f);
                v10 = fmaxf(v10, 0.f); v11 = fmaxf(v11, 0.f);
            }
            if (C32p) {
                *(float2*)&C32p[(long long)row * ldc + col] = make_float2(v00, v01);
                *(float2*)&C32p[(long long)(row + 8) * ldc + col] = make_float2(v10, v11);
            }
            if (C16p) {
                *(__half2*)&C16p[(long long)row * ldc + col] = __floats2half2_rn(v00, v01);
                *(__half2*)&C16p[(long long)(row + 8) * ldc + col] = __floats2half2_rn(v10, v11);
            }
        }
    }
    pdl_go();
}

// ============ fused softmax + attn@V (R12/R13 champion) ====================
#define PPITCH 392
#define BPITCH 72
#define P_BYTES (64 * PPITCH * 2)
#define BV_BYTES (384 * BPITCH * 2)
#define ATT_SMEM (P_BYTES + BV_BYTES)

__global__ void __launch_bounds__(128) attn_pv(
    const float* __restrict__ SC,
    const __half* __restrict__ V,
    __half* __restrict__ O,
    int d, int hd)
{
    extern __shared__ char smraw[];
    __half* P = (__half*)smraw;
    uint32_t Pb = (uint32_t)__cvta_generic_to_shared(P);
    uint32_t Bb = Pb + P_BYTES;

    pdl_wait();

    int tid = threadIdx.x;
    int warp = tid >> 5, lane = tid & 31;
    int g = lane >> 2, tg = lane & 3;
    int wm = (warp >> 1) * 32, wn = (warp & 1) * 32;
    int z = blockIdx.z;
    int m0 = blockIdx.y * 64;
    int nc0 = blockIdx.x * 64;
    const float* sc = SC + (long long)z * N_TOK * N_TOK;
    const __half* Vb = V + (long long)z * hd + nc0;

#pragma unroll
    for (int j = 0; j < 24; j++) {
        int c = tid + j * 128;
        int k = c >> 3, q = (c & 7) * 8;
        cpa16(Bb + (uint32_t)k * 144u + (uint32_t)q * 2u,
              Vb + (long long)k * (3 * d) + q);
    }
    cpa_commit();

    {
        int r = tid >> 1, h = tid & 1;
        const float* row = sc + (long long)(m0 + r) * N_TOK + h * 192;
        float mx = -1e30f;
        for (int c = 0; c < 192; c += 4) {
            float4 v = *(const float4*)(row + c);
            mx = fmaxf(mx, fmaxf(fmaxf(v.x, v.y), fmaxf(v.z, v.w)));
        }
        mx = fmaxf(mx, __shfl_xor_sync(0xffffffffu, mx, 1));
        __half* pr = P + r * PPITCH + h * 192;
        float sm = 0.f;
        for (int c = 0; c < 192; c += 4) {
            float4 v = *(const float4*)(row + c);
            float e0 = expf(v.x - mx), e1 = expf(v.y - mx);
            float e2 = expf(v.z - mx), e3 = expf(v.w - mx);
            sm += (e0 + e1) + (e2 + e3);
            *(__half2*)(pr + c)     = __floats2half2_rn(e0, e1);
            *(__half2*)(pr + c + 2) = __floats2half2_rn(e2, e3);
        }
        sm += __shfl_xor_sync(0xffffffffu, sm, 1);
        float inv = 1.0f / sm;
        __half2 hinv = __floats2half2_rn(inv, inv);
        for (int c = 0; c < 192; c += 2) {
            __half2* p2 = (__half2*)(pr + c);
            *p2 = __hmul2(*p2, hinv);
        }
    }
    cpa_wait<0>();
    __syncthreads();

    int aRow = (lane & 7) + ((lane >> 3) & 1) * 8;
    int aK   = ((lane >> 4) & 1) * 8;
    int tKr  = ((lane >> 3) & 1) * 8 + (lane & 7);
    int tNc  = ((lane >> 4) & 1) * 8;

    float acc[2][4][4] = {};
    unsigned afr[2][2][4], bfr[2][2][4];

    auto loadFrag = [&](int ks, int buf) {
        int kb = ks * 16;
#pragma unroll
        for (int mt = 0; mt < 2; mt++)
            ldsm_x4(afr[buf][mt],
                    Pb + (uint32_t)(wm + mt * 16 + aRow) * 784u
                       + (uint32_t)(kb + aK) * 2u);
#pragma unroll
        for (int p = 0; p < 2; p++)
            ldsm_x4_t(bfr[buf][p],
                      Bb + (uint32_t)(kb + tKr) * 144u
                         + (uint32_t)(wn + p * 16 + tNc) * 2u);
    };

    loadFrag(0, 0);
#pragma unroll
    for (int ks = 0; ks < 24; ks++) {
        int buf = ks & 1;
        if (ks < 23) loadFrag(ks + 1, buf ^ 1);
#pragma unroll
        for (int mt = 0; mt < 2; mt++)
#pragma unroll
            for (int nt = 0; nt < 4; nt++)
                mma16h(acc[mt][nt], afr[buf][mt], &bfr[buf][nt >> 1][(nt & 1) * 2]);
    }

#pragma unroll
    for (int mt = 0; mt < 2; mt++) {
#pragma unroll
        for (int nt = 0; nt < 4; nt++) {
            int row = m0 + wm + mt * 16 + g;
            int col = z * hd + nc0 + wn + nt * 8 + 2 * tg;
            *(__half2*)&O[(long long)row * d + col] =
                __floats2half2_rn(acc[mt][nt][0], acc[mt][nt][1]);
            *(__half2*)&O[(long long)(row + 8) * d + col] =
                __floats2half2_rn(acc[mt][nt][2], acc[mt][nt][3]);
        }
    }
    pdl_go();
}

// ---------------- x = LN(x + delta); fp16 shadow ----------------
__global__ void ln_res_kernel(float* __restrict__ x, __half* __restrict__ xh,
                              const float* __restrict__ delta,
                              const float* __restrict__ s, const float* __restrict__ b, int d) {
    pdl_wait();
    float* xr = x + (long long)blockIdx.x * d;
    __half* xhr = xh + (long long)blockIdx.x * d;
    const float* dr = delta + (long long)blockIdx.x * d;
    __shared__ float red[256];
    int tid = threadIdx.x;
    float sum = 0.f;
    for (int j = tid; j < d; j += 256) { float v = xr[j] + dr[j]; xr[j] = v; sum += v; }
    red[tid] = sum; __syncthreads();
    for (int off = 128; off; off >>= 1) {
        if (tid < off) red[tid] += red[tid + off];
        __syncthreads();
    }
    float mean = red[0] / d; __syncthreads();
    float s2 = 0.f;
    for (int j = tid; j < d; j += 256) { float v = xr[j] - mean; s2 += v * v; }
    red[tid] = s2; __syncthreads();
    for (int off = 128; off; off >>= 1) {
        if (tid < off) red[tid] += red[tid + off];
        __syncthreads();
    }
    float inv = rsqrtf(red[0] / d + 1e-5f);
    __syncthreads();
    for (int j = tid; j < d; j += 256) {
        float v = (xr[j] - mean) * inv * s[j] + b[j];
        xr[j] = v;
        xhr[j] = __float2half(v);
    }
    pdl_go();
}

// ---------------- final linear ----------------
__global__ void lin_kernel(const float* __restrict__ x, const float* __restrict__ w,
                           const float* __restrict__ b, float* __restrict__ a,
                           float* __restrict__ c) {
    pdl_wait();
    int i = blockIdx.x;
    const float* xr = x + (long long)i * CDIM;
    __shared__ float red[4][256];
    int tid = threadIdx.x;
    float s0 = 0, s1 = 0, s2 = 0, s3 = 0;
    for (int k = tid; k < CDIM; k += 256) {
        float xv = xr[k];
        s0 += xv * w[k];
        s1 += xv * w[2 * CDIM + k];
        s2 += xv * w[CDIM + k];
        s3 += xv * w[2 * CDIM + CDIM + k];
    }
    red[0][tid] = s0; red[1][tid] = s1; red[2][tid] = s2; red[3][tid] = s3;
    __syncthreads();
    for (int off = 128; off; off >>= 1) {
        if (tid < off) {
            red[0][tid] += red[0][tid + off];
            red[1][tid] += red[1][tid + off];
            red[2][tid] += red[2][tid + off];
            red[3][tid] += red[3][tid + off];
        }
        __syncthreads();
    }
    if (tid == 0) {
        a[2 * i]     = red[0][0] + b[0];
        a[2 * i + 1] = red[1][0] + b[1];
        c[2 * i]     = red[2][0];
        c[2 * i + 1] = red[3][0];
    }
    pdl_go();
}

// ---------------- pairwise probs + loss partials ----------------
__global__ void pair_kernel(const float* __restrict__ a, const float* __restrict__ c,
                            const int* __restrict__ gt, float* __restrict__ probs,
                            float* __restrict__ rowcell, float* __restrict__ rowlink) {
    pdl_wait();
    int i = blockIdx.x, j = threadIdx.x;
    float l0 = a[2 * i] + c[2 * j];
    float l1 = a[2 * i + 1] + c[2 * j + 1];
    float m = fmaxf(l0, l1);
    float e0 = expf(l0 - m), e1 = expf(l1 - m);
    float inv = 1.0f / (e0 + e1);
    float p0 = e0 * inv, p1 = e1 * inv;
    long long idx = ((long long)i * N_TOK + j) * 2;
    probs[idx] = p0; probs[idx + 1] = p1;
    float mm = fmaxf(p0, p1);
    float lse = mm + logf(expf(p0 - mm) + expf(p1 - mm));
    float pg = gt[i * N_TOK + j] ? p1 : p0;
    float cell = lse - pg;

    __shared__ float red[512];
    red[j] = cell;
    if (j < 128) red[384 + j] = 0.f;
    __syncthreads();
    for (int off = 256; off; off >>= 1) {
        if (j < off) red[j] += red[j + off];
        __syncthreads();
    }
    if (j == 0) rowcell[i] = red[0];
    __syncthreads();
    red[j] = p1;
    if (j < 128) red[384 + j] = 0.f;
    __syncthreads();
    for (int off = 256; off; off >>= 1) {
        if (j < off) red[j] += red[j + off];
        __syncthreads();
    }
    if (j == 0) rowlink[i] = red[0];
    pdl_go();
}

__global__ void col_kernel(const float* __restrict__ probs, float* __restrict__ collink) {
    pdl_wait();
    int j = blockIdx.x; int tid = threadIdx.x;
    float s = 0.f;
    for (int i = tid; i < N_TOK; i += 128) s += probs[((long long)i * N_TOK + j) * 2 + 1];
    __shared__ float red[128];
    red[tid] = s; __syncthreads();
    for (int off = 64; off; off >>= 1) {
        if (tid < off) red[tid] += red[tid + off];
        __syncthreads();
    }
    if (tid == 0) collink[j] = red[0];
    pdl_go();
}

__global__ void final_kernel(const float* __restrict__ rowcell, const float* __restrict__ rowlink,
                             const float* __restrict__ collink, float* __restrict__ out,
                             int out_size) {
    pdl_wait();
    __shared__ float r1[512], r2[512];
    int tid = threadIdx.x;
    r1[tid] = (tid < N_TOK) ? rowcell[tid] : 0.f;
    r2[tid] = (tid < N_TOK - 1) ? fabsf(rowlink[tid] + collink[tid] - 1.0f) : 0.f;
    __syncthreads();
    for (int off = 256; off; off >>= 1) {
        if (tid < off) { r1[tid] += r1[tid + off]; r2[tid] += r2[tid + off]; }
        __syncthreads();
    }
    if (tid == 0 && out_size >= N_TOK * N_TOK * 2 + 2) {
        out[N_TOK * N_TOK * 2]     = r1[0] / (float)N_TOK;
        out[N_TOK * N_TOK * 2 + 1] = r2[0];
    }
}

// ---------------- host orchestration (PDL launches) ----------------
static cudaLaunchAttribute g_attr[1];
template <typename F, typename... Args>
static inline void pl(F f, dim3 gr, dim3 bl, size_t sm, Args... args) {
    cudaLaunchConfig_t c = {};
    c.gridDim = gr; c.blockDim = bl; c.dynamicSmemBytes = sm; c.stream = 0;
    g_attr[0].id = cudaLaunchAttributeProgrammaticStreamSerialization;
    g_attr[0].val.programmaticStreamSerializationAllowed = 1;
    c.attrs = g_attr; c.numAttrs = 1;
    cudaLaunchKernelEx(&c, f, args...);
}

struct EncW {
    const __half *qkv_h, *out_h, *ff1_h, *ff2_h;
    const float *qkv_b, *out_b, *ln1_s, *ln1_b, *ff1_b, *ff2_b, *ln2_s, *ln2_b;
};

static void run_encoder(float* x, __half* xh, int d, const EncW& w,
                        __half* qkvh, float* sc, __half* oh,
                        float* y, __half* hh) {
    const int M = N_TOK;
    const int hd = d / NH;
    const float scale = 1.0f / sqrtf((float)hd);
    for (int l = 0; l < NLAYERS; l++) {
        pl(h16_nt, dim3(3 * d / 64, M / 64, 1), dim3(128), H_SMEM,
           (const __half*)xh, d, 0LL, w.qkv_h + (long long)l * 3 * d * d, d, 0LL,
           w.qkv_b + (long long)l * 3 * d, (float*)0, qkvh, 3 * d, 0LL, d, 1.f, 0);
        pl(h16_nt, dim3(M / 64, M / 64, NH), dim3(128), H_SMEM,
           (const __half*)qkvh, 3 * d, (long long)hd, (const __half*)(qkvh + d), 3 * d, (long long)hd,
           (const float*)0, sc, (__half*)0, M, (long long)M * M, hd, scale, 0);
        pl(attn_pv, dim3(hd / 64, M / 64, NH), dim3(128), ATT_SMEM,
           (const float*)sc, (const __half*)(qkvh + 2 * d), oh, d, hd);
        pl(h16_nt, dim3(d / 64, M / 64, 1), dim3(128), H_SMEM,
           (const __half*)oh, d, 0LL, w.out_h + (long long)l * d * d, d, 0LL,
           w.out_b + (long long)l * d, y, (__half*)0, d, 0LL, d, 1.f, 0);
        pl(ln_res_kernel, dim3(M), dim3(256), 0,
           x, xh, (const float*)y, w.ln1_s + (long long)l * d, w.ln1_b + (long long)l * d, d);
        pl(h16_nt, dim3(FF_DIM / 64, M / 64, 1), dim3(128), H_SMEM,
           (const __half*)xh, d, 0LL, w.ff1_h + (long long)l * FF_DIM * d, d, 0LL,
           w.ff1_b + (long long)l * FF_DIM, (float*)0, hh, FF_DIM, 0LL, d, 1.f, 1);
        pl(h16_nt, dim3(d / 64, M / 64, 1), dim3(128), H_SMEM,
           (const __half*)hh, FF_DIM, 0LL, w.ff2_h + (long long)l * d * FF_DIM, FF_DIM, 0LL,
           w.ff2_b + (long long)l * d, y, (__half*)0, d, 0LL, FF_DIM, 1.f, 0);
        pl(ln_res_kernel, dim3(M), dim3(256), 0,
           x, xh, (const float*)y, w.ln2_s + (long long)l * d, w.ln2_b + (long long)l * d, d);
    }
}

extern "C" void kernel_launch(void* const* d_in, const int* in_sizes, int n_in,
                              void* d_out, int out_size) {
    const float* text   = (const float*)d_in[0];
    const float* vision = (const float*)d_in[1];
    const int*   gt     = (const int*)d_in[2];
    const float* lin_w  = (const float*)d_in[27];
    const float* lin_b  = (const float*)d_in[28];

    static int inited = 0;
    if (!inited) {
        cudaFuncSetAttribute(h16_nt, cudaFuncAttributeMaxDynamicSharedMemorySize, H_SMEM);
        cudaFuncSetAttribute(attn_pv, cudaFuncAttributeMaxDynamicSharedMemorySize, ATT_SMEM);
        inited = 1;
    }

    float* buf = nullptr;
    cudaGetSymbolAddress((void**)&buf, g_buf);
    __half* hb = nullptr;
    cudaGetSymbolAddress((void**)&hb, g_hbuf);

    float* x    = buf + OFF_X;
    float* x2   = buf + OFF_X2;
    float* sc   = buf + OFF_SC;
    float* y    = buf + OFF_Y;
    float* ga   = buf + OFF_A;
    float* gc   = buf + OFF_C;
    float* rcel = buf + OFF_RC;
    float* rlnk = buf + OFF_RL;
    float* clnk = buf + OFF_CL;

    __half* qkvh = hb + HA_QKV;
    __half* xh   = hb + HA_X;
    __half* oh   = hb + HA_O;
    __half* hh   = hb + HA_H;

    // one launch: convert all weights + copy text into x/xh (all pure inputs)
    ConvArgs ca;
    const long long offs[8] = {HW_TQKV, HW_TOUT, HW_TFF1, HW_TFF2,
                               HW_CQKV, HW_COUT, HW_CFF1, HW_CFF2};
    const int srcs[8] = {3, 5, 9, 11, 15, 17, 21, 23};
    const long long ns[8] = {3538944LL, 1179648LL, 3145728LL, 3145728LL,
                             14155776LL, 4718592LL, 6291456LL, 6291456LL};
    ca.cum[0] = 0;
    for (int i = 0; i < 8; i++) {
        ca.src[i] = (const float*)d_in[srcs[i]];
        ca.dstOff[i] = offs[i];
        ca.cum[i + 1] = ca.cum[i] + (int)(ns[i] / 4);
    }
    ca.text = text; ca.x = x; ca.xh = xh;
    ca.textN4 = N_TOK * TDIM / 4;
    int total = ca.cum[8] + ca.textN4;
    pl(conv_all, dim3((total + 255) / 256), dim3(256), 0, ca, hb);

    EncW tw = {
        hb + HW_TQKV, hb + HW_TOUT, hb + HW_TFF1, hb + HW_TFF2,
        (const float*)d_in[4], (const float*)d_in[6],
        (const float*)d_in[7], (const float*)d_in[8],
        (const float*)d_in[10], (const float*)d_in[12],
        (const float*)d_in[13], (const float*)d_in[14]
    };
    EncW cw = {
        hb + HW_CQKV, hb + HW_COUT, hb + HW_CFF1, hb + HW_CFF2,
        (const float*)d_in[16], (const float*)d_in[18],
        (const float*)d_in[19], (const float*)d_in[20],
        (const float*)d_in[22], (const float*)d_in[24],
        (const float*)d_in[25], (const float*)d_in[26]
    };

    run_encoder(x, xh, TDIM, tw, qkvh, sc, oh, y, hh);

    pl(concat_k, dim3((N_TOK * CDIM + 255) / 256), dim3(256), 0, x2, xh, (const float*)x, vision);
    run_encoder(x2, xh, CDIM, cw, qkvh, sc, oh, y, hh);

    pl(lin_kernel, dim3(N_TOK), dim3(256), 0, (const float*)x2, lin_w, lin_b, ga, gc);

    float* out = (float*)d_out;
    pl(pair_kernel, dim3(N_TOK), dim3(N_TOK), 0,
       (const float*)ga, (const float*)gc, gt, out, rcel, rlnk);
    pl(col_kernel, dim3(N_TOK), dim3(128), 0, (const float*)out, clnk);
    pl(final_kernel, dim3(1), dim3(512), 0,
       (const float*)rcel, (const float*)rlnk, (const float*)clnk, out, out_size);
}